// round 1
// baseline (speedup 1.0000x reference)
#include <cuda_runtime.h>
#include <math.h>

// Problem constants (fixed shapes from the reference)
#define B_TOT  8192
#define SEQ    100
#define INF    15      // input features
#define HID    128
#define GATES  512     // 4*HID
#define FUT    30
#define ROWS   32      // batch rows per CTA
#define NCTA   (B_TOT / ROWS)   // 256
#define NTHR   256
#define KT     16      // K tile
#define WTS    516     // padded Wt row stride (floats) to soften STS conflicts

struct Smem {
    float h0[ROWS][HID];
    float c0[ROWS][HID];
    float h1[ROWS][HID];
    float c1[ROWS][HID];
    float Wt[KT][WTS];      // transposed weight tile: Wt[k][gate_col]
    float xbuf[ROWS][16];   // layer-0 input (x_t during enc, fed-back inp during dec)
    float fcw[2][HID];
};

__device__ __forceinline__ float sigf(float x) { return 1.0f / (1.0f + expf(-x)); }

// Load a [KTILE x 512] transposed tile of W (row-major [512][Kfull]) into Wt.
// KTILE==16, k0 multiple of 16, Kfull multiple of 4: vectorized float4 path.
__device__ __forceinline__ void load_tile16(float Wt[KT][WTS],
                                            const float* __restrict__ Wg,
                                            int Kfull, int k0, int tid) {
#pragma unroll
    for (int i = tid; i < GATES * 4; i += NTHR) {
        int jr = i >> 2;
        int kq = i & 3;
        float4 v = *reinterpret_cast<const float4*>(Wg + (size_t)jr * Kfull + k0 + kq * 4);
        Wt[kq * 4 + 0][jr] = v.x;
        Wt[kq * 4 + 1][jr] = v.y;
        Wt[kq * 4 + 2][jr] = v.z;
        Wt[kq * 4 + 3][jr] = v.w;
    }
}

// Scalar tile load for the K=15 x-projection (w_ih0 is [512][15])
__device__ __forceinline__ void load_tile_x(float Wt[KT][WTS],
                                            const float* __restrict__ Wg, int tid) {
    for (int i = tid; i < GATES * INF; i += NTHR) {
        int jr = i / INF;
        int k  = i - jr * INF;
        Wt[k][jr] = Wg[i];
    }
}

// acc[r][g] += sum_k As[r][k0+k] * Wt[k][j + g*128]
template <int KTILE>
__device__ __forceinline__ void mm_tile(float acc[16][4],
                                        const float Wt[KT][WTS],
                                        const float* __restrict__ As,
                                        int astride, int k0, int j) {
#pragma unroll 4
    for (int k = 0; k < KTILE; ++k) {
        float w0 = Wt[k][j];
        float w1 = Wt[k][j + HID];
        float w2 = Wt[k][j + 2 * HID];
        float w3 = Wt[k][j + 3 * HID];
#pragma unroll
        for (int r = 0; r < 16; ++r) {
            float a = As[r * astride + k0 + k];
            acc[r][0] = fmaf(a, w0, acc[r][0]);
            acc[r][1] = fmaf(a, w1, acc[r][1]);
            acc[r][2] = fmaf(a, w2, acc[r][2]);
            acc[r][3] = fmaf(a, w3, acc[r][3]);
        }
    }
}

__global__ void __launch_bounds__(NTHR, 2)
lstm_traj_kernel(const float* __restrict__ x,
                 const float* __restrict__ w_ih0, const float* __restrict__ w_hh0,
                 const float* __restrict__ b_ih0, const float* __restrict__ b_hh0,
                 const float* __restrict__ w_ih1, const float* __restrict__ w_hh1,
                 const float* __restrict__ b_ih1, const float* __restrict__ b_hh1,
                 const float* __restrict__ fc_w, const float* __restrict__ fc_b,
                 float* __restrict__ out) {
    extern __shared__ char smraw[];
    Smem& sm = *reinterpret_cast<Smem*>(smraw);

    const int tid   = threadIdx.x;
    const int j     = tid & (HID - 1);   // hidden unit owned by this thread
    const int rg    = tid >> 7;          // row group 0/1
    const int r0    = rg * 16;           // first of 16 rows this thread owns
    const int brow0 = blockIdx.x * ROWS;

    // zero state, stage fc_w
    for (int i = tid; i < ROWS * HID; i += NTHR) {
        (&sm.h0[0][0])[i] = 0.0f;
        (&sm.c0[0][0])[i] = 0.0f;
        (&sm.h1[0][0])[i] = 0.0f;
        (&sm.c1[0][0])[i] = 0.0f;
    }
    for (int i = tid; i < 2 * HID; i += NTHR) (&sm.fcw[0][0])[i] = fc_w[i];

    // per-thread combined biases (gate order: i, f, g, o)
    const float bi0 = b_ih0[j]           + b_hh0[j];
    const float bf0 = b_ih0[HID + j]     + b_hh0[HID + j];
    const float bg0 = b_ih0[2 * HID + j] + b_hh0[2 * HID + j];
    const float bo0 = b_ih0[3 * HID + j] + b_hh0[3 * HID + j];
    const float bi1 = b_ih1[j]           + b_hh1[j];
    const float bf1 = b_ih1[HID + j]     + b_hh1[HID + j];
    const float bg1 = b_ih1[2 * HID + j] + b_hh1[2 * HID + j];
    const float bo1 = b_ih1[3 * HID + j] + b_hh1[3 * HID + j];
    __syncthreads();

    for (int t = 0; t < SEQ + FUT; ++t) {
        const bool enc = (t < SEQ);

        // stage layer-0 input for this step (encoder only; decoder keeps xbuf)
        if (enc) {
            for (int i = tid; i < ROWS * INF; i += NTHR) {
                int r = i / INF;
                int c = i - r * INF;
                sm.xbuf[r][c] = x[(size_t)(brow0 + r) * (SEQ * INF) + (size_t)t * INF + c];
            }
        }

        // ================= layer 0 =================
        float acc[16][4];
#pragma unroll
        for (int r = 0; r < 16; ++r) {
            acc[r][0] = bi0; acc[r][1] = bf0; acc[r][2] = bg0; acc[r][3] = bo0;
        }
        // x @ w_ih0^T
        __syncthreads();                       // xbuf written + previous Wt readers done
        load_tile_x(sm.Wt, w_ih0, tid);
        __syncthreads();
        mm_tile<INF>(acc, sm.Wt, &sm.xbuf[r0][0], 16, 0, j);
        // h0 @ w_hh0^T
#pragma unroll 1
        for (int k0 = 0; k0 < HID; k0 += KT) {
            __syncthreads();
            load_tile16(sm.Wt, w_hh0, HID, k0, tid);
            __syncthreads();
            mm_tile<KT>(acc, sm.Wt, &sm.h0[r0][0], HID, k0, j);
        }
        // epilogue layer 0 (writes h0/c0; mm readers of old h0 must be done)
        __syncthreads();
#pragma unroll
        for (int r = 0; r < 16; ++r) {
            float ig = sigf(acc[r][0]);
            float fg = sigf(acc[r][1]);
            float gg = tanhf(acc[r][2]);
            float og = sigf(acc[r][3]);
            float c  = fg * sm.c0[r0 + r][j] + ig * gg;
            sm.c0[r0 + r][j] = c;
            sm.h0[r0 + r][j] = og * tanhf(c);
        }

        // ================= layer 1 =================
#pragma unroll
        for (int r = 0; r < 16; ++r) {
            acc[r][0] = bi1; acc[r][1] = bf1; acc[r][2] = bg1; acc[r][3] = bo1;
        }
        // h0(new) @ w_ih1^T
#pragma unroll 1
        for (int k0 = 0; k0 < HID; k0 += KT) {
            __syncthreads();                   // also orders epilogue-0 h0 writes
            load_tile16(sm.Wt, w_ih1, HID, k0, tid);
            __syncthreads();
            mm_tile<KT>(acc, sm.Wt, &sm.h0[r0][0], HID, k0, j);
        }
        // h1 @ w_hh1^T
#pragma unroll 1
        for (int k0 = 0; k0 < HID; k0 += KT) {
            __syncthreads();
            load_tile16(sm.Wt, w_hh1, HID, k0, tid);
            __syncthreads();
            mm_tile<KT>(acc, sm.Wt, &sm.h1[r0][0], HID, k0, j);
        }
        // epilogue layer 1
        __syncthreads();
#pragma unroll
        for (int r = 0; r < 16; ++r) {
            float ig = sigf(acc[r][0]);
            float fg = sigf(acc[r][1]);
            float gg = tanhf(acc[r][2]);
            float og = sigf(acc[r][3]);
            float c  = fg * sm.c1[r0 + r][j] + ig * gg;
            sm.c1[r0 + r][j] = c;
            sm.h1[r0 + r][j] = og * tanhf(c);
        }

        // ================= decoder head =================
        if (!enc) {
            __syncthreads();                   // h1 fully written
            if (tid < 64) {
                int r = tid >> 1;
                int o = tid & 1;
                float s = fc_b[o];
                for (int jj = 0; jj < HID; ++jj)
                    s += sm.h1[r][jj] * sm.fcw[o][jj];
                int f = t - SEQ;
                out[(size_t)(brow0 + r) * (FUT * 2) + f * 2 + o] = s;
                sm.xbuf[r][o] = s;             // feed back into features 0:2
            }
            // next iteration's first __syncthreads orders xbuf for all threads
        }
    }
}

extern "C" void kernel_launch(void* const* d_in, const int* in_sizes, int n_in,
                              void* d_out, int out_size) {
    const float* x     = (const float*)d_in[0];
    const float* w_ih0 = (const float*)d_in[1];
    const float* w_hh0 = (const float*)d_in[2];
    const float* b_ih0 = (const float*)d_in[3];
    const float* b_hh0 = (const float*)d_in[4];
    const float* w_ih1 = (const float*)d_in[5];
    const float* w_hh1 = (const float*)d_in[6];
    const float* b_ih1 = (const float*)d_in[7];
    const float* b_hh1 = (const float*)d_in[8];
    const float* fc_w  = (const float*)d_in[9];
    const float* fc_b  = (const float*)d_in[10];
    float* out = (float*)d_out;

    cudaFuncSetAttribute(lstm_traj_kernel,
                         cudaFuncAttributeMaxDynamicSharedMemorySize,
                         (int)sizeof(Smem));
    lstm_traj_kernel<<<NCTA, NTHR, sizeof(Smem)>>>(
        x, w_ih0, w_hh0, b_ih0, b_hh0, w_ih1, w_hh1, b_ih1, b_hh1, fc_w, fc_b, out);
}

// round 2
// speedup vs baseline: 1.5242x; 1.5242x over previous
#include <cuda_runtime.h>
#include <math.h>

#define B_TOT  8192
#define SEQ    100
#define INF    15
#define HID    128
#define FUT    30
#define ROWS   32
#define RP     36                 // padded row stride (floats); 36/4=9 odd -> conflict-free LDS.128
#define NCTA   (B_TOT / ROWS)     // 256
#define NTHR   256

typedef unsigned long long ull;

// ---- transposed, gate-interleaved weights: [k][j][4 gates] as float4 ----
// segments (float4 units): X:0(+1920)  H0:1920(+16384)  I1:18304(+16384)  H1:34688(+16384)
#define OFF_X   0
#define OFF_H0  1920
#define OFF_I1  18304
#define OFF_H1  34688
#define WT_TOT4 51072
__device__ float4 g_wt4[WT_TOT4];

__global__ void transpose_weights(const float* __restrict__ w_ih0,
                                  const float* __restrict__ w_hh0,
                                  const float* __restrict__ w_ih1,
                                  const float* __restrict__ w_hh1) {
    int idx = blockIdx.x * blockDim.x + threadIdx.x;
    if (idx >= WT_TOT4) return;
    const float* W; int K; int local;
    if      (idx < OFF_H0) { W = w_ih0; K = INF; local = idx; }
    else if (idx < OFF_I1) { W = w_hh0; K = HID; local = idx - OFF_H0; }
    else if (idx < OFF_H1) { W = w_ih1; K = HID; local = idx - OFF_I1; }
    else                   { W = w_hh1; K = HID; local = idx - OFF_H1; }
    int k = local >> 7;
    int j = local & 127;
    float4 v;
    v.x = W[(0 * HID + j) * K + k];   // gate i
    v.y = W[(1 * HID + j) * K + k];   // gate f
    v.z = W[(2 * HID + j) * K + k];   // gate g
    v.w = W[(3 * HID + j) * K + k];   // gate o
    g_wt4[idx] = v;
}

// ---- packed f32x2 helpers ----
__device__ __forceinline__ ull pk2(float x, float y) {
    ull r; asm("mov.b64 %0,{%1,%2};" : "=l"(r) : "f"(x), "f"(y)); return r;
}
__device__ __forceinline__ void fma2(ull& d, ull a, ull b) {
    asm("fma.rn.f32x2 %0, %1, %2, %0;" : "+l"(d) : "l"(a), "l"(b));
}
__device__ __forceinline__ float2 up2(ull v) {
    float2 r; asm("mov.b64 {%0,%1},%2;" : "=f"(r.x), "=f"(r.y) : "l"(v)); return r;
}

__device__ __forceinline__ float sigf(float x) {
    return __fdividef(1.0f, 1.0f + __expf(-x));
}
__device__ __forceinline__ float tanhfast(float x) {
    return 1.0f - __fdividef(2.0f, __expf(2.0f * x) + 1.0f);
}

struct Smem {
    float h0t[HID][RP];
    float c0t[HID][RP];
    float h1t[HID][RP];
    float c1t[HID][RP];
    float xt[16][RP];      // layer-0 input, k-major (row 15 unused)
    float fcw[2][HID];
};

// acc[p][g] (+=) packed row-pair p (rows r0+2p, r0+2p+1) for gate g.
// At: k-major activations with row stride RP. Wt: gate-interleaved float4 per (k,j).
template <int K>
__device__ __forceinline__ void mm_acc(ull acc[8][4],
                                       const float* __restrict__ At,
                                       const float4* __restrict__ Wt,
                                       int j, int r0) {
#pragma unroll 4
    for (int k = 0; k < K; ++k) {
        float4 w = __ldg(&Wt[k * HID + j]);
        ull w0 = pk2(w.x, w.x);
        ull w1 = pk2(w.y, w.y);
        ull w2 = pk2(w.z, w.z);
        ull w3 = pk2(w.w, w.w);
        const float* a = At + k * RP + r0;
        ulonglong2 q0 = *reinterpret_cast<const ulonglong2*>(a);
        ulonglong2 q1 = *reinterpret_cast<const ulonglong2*>(a + 4);
        ulonglong2 q2 = *reinterpret_cast<const ulonglong2*>(a + 8);
        ulonglong2 q3 = *reinterpret_cast<const ulonglong2*>(a + 12);
        ull av[8] = {q0.x, q0.y, q1.x, q1.y, q2.x, q2.y, q3.x, q3.y};
#pragma unroll
        for (int p = 0; p < 8; ++p) {
            fma2(acc[p][0], av[p], w0);
            fma2(acc[p][1], av[p], w1);
            fma2(acc[p][2], av[p], w2);
            fma2(acc[p][3], av[p], w3);
        }
    }
}

// LSTM gate epilogue: consumes acc, updates c (SMEM, thread-private column) and h.
__device__ __forceinline__ void epilogue(ull acc[8][4], float* hb, float* cb) {
#pragma unroll
    for (int p = 0; p < 8; ++p) {
        float2 gi = up2(acc[p][0]);
        float2 gf = up2(acc[p][1]);
        float2 gg = up2(acc[p][2]);
        float2 go = up2(acc[p][3]);
        float cA = sigf(gf.x) * cb[2 * p]     + sigf(gi.x) * tanhfast(gg.x);
        float cB = sigf(gf.y) * cb[2 * p + 1] + sigf(gi.y) * tanhfast(gg.y);
        cb[2 * p]     = cA;
        cb[2 * p + 1] = cB;
        hb[2 * p]     = sigf(go.x) * tanhfast(cA);
        hb[2 * p + 1] = sigf(go.y) * tanhfast(cB);
    }
}

__global__ void __launch_bounds__(NTHR, 2)
lstm_traj_kernel(const float* __restrict__ x,
                 const float* __restrict__ b_ih0, const float* __restrict__ b_hh0,
                 const float* __restrict__ b_ih1, const float* __restrict__ b_hh1,
                 const float* __restrict__ fc_w, const float* __restrict__ fc_b,
                 float* __restrict__ out) {
    extern __shared__ char smraw[];
    Smem& sm = *reinterpret_cast<Smem*>(smraw);

    const int tid   = threadIdx.x;
    const int j     = tid & (HID - 1);     // hidden unit owned by this thread
    const int r0    = (tid >> 7) * 16;     // first of 16 batch rows this thread owns
    const int brow0 = blockIdx.x * ROWS;

    const float4* WX  = g_wt4 + OFF_X;
    const float4* WH0 = g_wt4 + OFF_H0;
    const float4* WI1 = g_wt4 + OFF_I1;
    const float4* WH1 = g_wt4 + OFF_H1;

    // zero states, stage fc_w
    for (int i = tid; i < HID * RP; i += NTHR) {
        (&sm.h0t[0][0])[i] = 0.0f;
        (&sm.c0t[0][0])[i] = 0.0f;
        (&sm.h1t[0][0])[i] = 0.0f;
        (&sm.c1t[0][0])[i] = 0.0f;
    }
    if (tid < 2 * HID) (&sm.fcw[0][0])[tid] = fc_w[tid];

    // combined biases (gate order i, f, g, o)
    const float bi0 = b_ih0[j]           + b_hh0[j];
    const float bf0 = b_ih0[HID + j]     + b_hh0[HID + j];
    const float bg0 = b_ih0[2 * HID + j] + b_hh0[2 * HID + j];
    const float bo0 = b_ih0[3 * HID + j] + b_hh0[3 * HID + j];
    const float bi1 = b_ih1[j]           + b_hh1[j];
    const float bf1 = b_ih1[HID + j]     + b_hh1[HID + j];
    const float bg1 = b_ih1[2 * HID + j] + b_hh1[2 * HID + j];
    const float bo1 = b_ih1[3 * HID + j] + b_hh1[3 * HID + j];

    float* hb0 = &sm.h0t[j][r0];
    float* cb0 = &sm.c0t[j][r0];
    float* hb1 = &sm.h1t[j][r0];
    float* cb1 = &sm.c1t[j][r0];

    ull acc[8][4];

    for (int t = 0; t < SEQ + FUT; ++t) {
        const bool enc = (t < SEQ);

        if (enc) {
            // stage x_t transposed: xt[c][r]
            for (int i = tid; i < ROWS * INF; i += NTHR) {
                int r = i / INF;
                int c = i - r * INF;
                sm.xt[c][r] = x[(size_t)(brow0 + r) * (SEQ * INF) + (size_t)t * INF + c];
            }
        }
        __syncthreads();   // (A) xt visible (enc stage or decoder feedback)

        // ---- layer 0: gates = x @ Wih0^T + h0 @ Whh0^T + b0 ----
        {
            ull b0q = pk2(bi0, bi0), b1q = pk2(bf0, bf0);
            ull b2q = pk2(bg0, bg0), b3q = pk2(bo0, bo0);
#pragma unroll
            for (int p = 0; p < 8; ++p) {
                acc[p][0] = b0q; acc[p][1] = b1q; acc[p][2] = b2q; acc[p][3] = b3q;
            }
        }
        mm_acc<INF>(acc, &sm.xt[0][0],  WX,  j, r0);
        mm_acc<HID>(acc, &sm.h0t[0][0], WH0, j, r0);
        __syncthreads();   // (B) all reads of old h0t done
        epilogue(acc, hb0, cb0);
        __syncthreads();   // (C) new h0t visible

        // ---- layer 1: gates = h0 @ Wih1^T + h1 @ Whh1^T + b1 ----
        {
            ull b0q = pk2(bi1, bi1), b1q = pk2(bf1, bf1);
            ull b2q = pk2(bg1, bg1), b3q = pk2(bo1, bo1);
#pragma unroll
            for (int p = 0; p < 8; ++p) {
                acc[p][0] = b0q; acc[p][1] = b1q; acc[p][2] = b2q; acc[p][3] = b3q;
            }
        }
        mm_acc<HID>(acc, &sm.h0t[0][0], WI1, j, r0);
        mm_acc<HID>(acc, &sm.h1t[0][0], WH1, j, r0);
        __syncthreads();   // (D) all reads of old h1t done
        epilogue(acc, hb1, cb1);

        // ---- decoder head: pred = h1 @ fc_w^T + fc_b; feed back into xt[0:2] ----
        if (!enc) {
            __syncthreads();   // (E) new h1t visible
            if (tid < 64) {
                int r = tid >> 1;
                int o = tid & 1;
                float s = __ldg(&fc_b[o]);
                const float* fw = &sm.fcw[o][0];
#pragma unroll 8
                for (int jj = 0; jj < HID; ++jj)
                    s += sm.h1t[jj][r] * fw[jj];
                out[(size_t)(brow0 + r) * (FUT * 2) + (size_t)(t - SEQ) * 2 + o] = s;
                sm.xt[o][r] = s;   // autoregressive feedback into features 0:2
            }
            // next iteration's sync (A) publishes xt to all threads
        }
    }
}

extern "C" void kernel_launch(void* const* d_in, const int* in_sizes, int n_in,
                              void* d_out, int out_size) {
    const float* x     = (const float*)d_in[0];
    const float* w_ih0 = (const float*)d_in[1];
    const float* w_hh0 = (const float*)d_in[2];
    const float* b_ih0 = (const float*)d_in[3];
    const float* b_hh0 = (const float*)d_in[4];
    const float* w_ih1 = (const float*)d_in[5];
    const float* w_hh1 = (const float*)d_in[6];
    const float* b_ih1 = (const float*)d_in[7];
    const float* b_hh1 = (const float*)d_in[8];
    const float* fc_w  = (const float*)d_in[9];
    const float* fc_b  = (const float*)d_in[10];
    float* out = (float*)d_out;

    transpose_weights<<<(WT_TOT4 + 255) / 256, 256>>>(w_ih0, w_hh0, w_ih1, w_hh1);

    cudaFuncSetAttribute(lstm_traj_kernel,
                         cudaFuncAttributeMaxDynamicSharedMemorySize,
                         (int)sizeof(Smem));
    lstm_traj_kernel<<<NCTA, NTHR, sizeof(Smem)>>>(
        x, b_ih0, b_hh0, b_ih1, b_hh1, fc_w, fc_b, out);
}